// round 2
// baseline (speedup 1.0000x reference)
#include <cuda_runtime.h>
#include <cuda_bf16.h>
#include <math.h>

// Problem constants
#define B_   2
#define S_   2048
#define HID_ 2048
#define NH_  16
#define NKV_ 8
#define HD_  256
#define F_   8192      // (NH + 2*NKV) * HD
#define M1_  4096      // B*S
#define EPS_ 1e-6f
#define SCALE_ 0.0625f // 256^-0.5

// Scratch (device globals, no allocation)
__device__ float g_qkv[(size_t)M1_ * F_];    // 134 MB: qkv projection result (q|k|v per token)
__device__ float g_ao [(size_t)M1_ * (NH_*HD_)]; // 67 MB: attention output [bs][h*HD+d]

// ---------------------------------------------------------------------------
// Register-blocked SGEMM: C[M,N] = A[M,K] @ B[K,N], all row-major, fp32.
// M,N multiples of 128; K multiple of 16. 256 threads, 8x8 per thread.
// ---------------------------------------------------------------------------
#define BM 128
#define BN 128
#define BK 16
#define TM 8
#define TN 8

__global__ __launch_bounds__(256) void sgemm_kernel(
    const float* __restrict__ A, const float* __restrict__ Bm,
    float* __restrict__ C, int M, int N, int K)
{
    __shared__ float As[BK][BM];
    __shared__ float Bs[BK][BN];

    const int tid  = threadIdx.x;
    const int brow = blockIdx.y * BM;
    const int bcol = blockIdx.x * BN;

    const int a_r = tid >> 2;          // 0..63
    const int a_c = (tid & 3) << 2;    // 0,4,8,12
    const int b_r = tid >> 5;          // 0..7
    const int b_c = (tid & 31) << 2;   // 0..124

    const int tx = tid & 15;
    const int ty = tid >> 4;

    float acc[TM][TN];
    #pragma unroll
    for (int i = 0; i < TM; i++)
        #pragma unroll
        for (int j = 0; j < TN; j++) acc[i][j] = 0.f;

    for (int k0 = 0; k0 < K; k0 += BK) {
        float4 av0 = *(const float4*)&A[(size_t)(brow + a_r)      * K + k0 + a_c];
        float4 av1 = *(const float4*)&A[(size_t)(brow + a_r + 64) * K + k0 + a_c];
        As[a_c + 0][a_r] = av0.x; As[a_c + 1][a_r] = av0.y;
        As[a_c + 2][a_r] = av0.z; As[a_c + 3][a_r] = av0.w;
        As[a_c + 0][a_r + 64] = av1.x; As[a_c + 1][a_r + 64] = av1.y;
        As[a_c + 2][a_r + 64] = av1.z; As[a_c + 3][a_r + 64] = av1.w;

        float4 bv0 = *(const float4*)&Bm[(size_t)(k0 + b_r)     * N + bcol + b_c];
        float4 bv1 = *(const float4*)&Bm[(size_t)(k0 + b_r + 8) * N + bcol + b_c];
        *(float4*)&Bs[b_r][b_c]     = bv0;
        *(float4*)&Bs[b_r + 8][b_c] = bv1;

        __syncthreads();

        #pragma unroll
        for (int kk = 0; kk < BK; kk++) {
            float ra[TM], rb[TN];
            #pragma unroll
            for (int i = 0; i < TM; i++) ra[i] = As[kk][ty * TM + i];
            #pragma unroll
            for (int j = 0; j < TN; j++) rb[j] = Bs[kk][tx * TN + j];
            #pragma unroll
            for (int i = 0; i < TM; i++)
                #pragma unroll
                for (int j = 0; j < TN; j++)
                    acc[i][j] = fmaf(ra[i], rb[j], acc[i][j]);
        }
        __syncthreads();
    }

    #pragma unroll
    for (int i = 0; i < TM; i++) {
        float* crow = &C[(size_t)(brow + ty * TM + i) * N + bcol + tx * TN];
        *(float4*)(crow)     = make_float4(acc[i][0], acc[i][1], acc[i][2], acc[i][3]);
        *(float4*)(crow + 4) = make_float4(acc[i][4], acc[i][5], acc[i][6], acc[i][7]);
    }
}

// ---------------------------------------------------------------------------
// RMSNorm + RoPE, in-place on q and k heads of g_qkv.
// One block per (bs, head24) vector of HD=256. 256 threads.
// ---------------------------------------------------------------------------
__global__ __launch_bounds__(256) void norm_rope_kernel(
    float* __restrict__ qkv, const float* __restrict__ cosb,
    const float* __restrict__ sinb, const float* __restrict__ qw,
    const float* __restrict__ kw)
{
    const int blk = blockIdx.x;
    const int h24 = blk % (NH_ + NKV_);
    const int bs  = blk / (NH_ + NKV_);
    const int tid = threadIdx.x;

    const bool isq = (h24 < NH_);
    const int off  = isq ? h24 * HD_ : NH_ * HD_ + (h24 - NH_) * HD_;
    float* p = qkv + (size_t)bs * F_ + off;

    float x = p[tid];
    float ss = x * x;
    #pragma unroll
    for (int m = 16; m; m >>= 1) ss += __shfl_xor_sync(~0u, ss, m);

    __shared__ float warpsum[8];
    __shared__ float xn_s[HD_];
    if ((tid & 31) == 0) warpsum[tid >> 5] = ss;
    __syncthreads();
    float tot = warpsum[0] + warpsum[1] + warpsum[2] + warpsum[3]
              + warpsum[4] + warpsum[5] + warpsum[6] + warpsum[7];

    float inv = rsqrtf(tot * (1.0f / HD_) + EPS_);
    const float* w = isq ? qw : kw;
    float xn = x * inv * (1.0f + w[tid]);
    xn_s[tid] = xn;
    __syncthreads();

    float rot = (tid < HD_ / 2) ? -xn_s[tid + HD_ / 2] : xn_s[tid - HD_ / 2];
    float c = cosb[(size_t)bs * HD_ + tid];
    float s = sinb[(size_t)bs * HD_ + tid];
    p[tid] = xn * c + rot * s;
}

// ---------------------------------------------------------------------------
// Attention: one block per (b, h, 16-query tile). Two-pass: full score row
// in SMEM, block softmax, then PV. 256 threads, ~148KB dynamic SMEM.
// ---------------------------------------------------------------------------
#define BQ 16
#define QS_STRIDE 260   // 256 + 4 pad (float4-aligned, bank-spread)
#define SC_STRIDE 2049  // 2048 + 1 pad (bank-spread)
#define ATTN_SMEM_BYTES ((BQ * QS_STRIDE + BQ * SC_STRIDE) * 4)

__global__ __launch_bounds__(256) void attn_kernel(
    const float* __restrict__ qkv, float* __restrict__ aout)
{
    extern __shared__ float smem[];
    float* qs = smem;                   // [BQ][QS_STRIDE]
    float* sc = smem + BQ * QS_STRIDE;  // [BQ][SC_STRIDE]
    __shared__ float s_inv[BQ];

    const int tid  = threadIdx.x;
    const int blk  = blockIdx.x;
    const int qt   = blk % (S_ / BQ);
    const int bh   = blk / (S_ / BQ);
    const int h    = bh % NH_;
    const int b    = bh / NH_;
    const int kvh  = h / (NH_ / NKV_);
    const int q0   = qt * BQ;

    const float* batch_base = qkv + (size_t)b * S_ * F_;
    const float* qbase = batch_base + (size_t)q0 * F_ + h * HD_;

    // Load Q tile
    for (int i = tid; i < BQ * HD_; i += 256) {
        int rr = i >> 8, dd = i & 255;
        qs[rr * QS_STRIDE + dd] = qbase[(size_t)rr * F_ + dd];
    }
    __syncthreads();

    // Score pass: each lane owns (row = lane&15, key parity = lane>>4).
    {
        const int lane = tid & 31;
        const int warp = tid >> 5;
        const int r  = lane & 15;
        const int kk = lane >> 4;
        const float* kbase = batch_base + NH_ * HD_ + kvh * HD_;
        const float4* qrow = (const float4*)(qs + r * QS_STRIDE);

        for (int kp = warp; kp < S_ / 2; kp += 8) {
            const int k = kp * 2 + kk;
            const float4* krow = (const float4*)(kbase + (size_t)k * F_);
            float acc = 0.f;
            #pragma unroll 8
            for (int d4 = 0; d4 < HD_ / 4; d4++) {
                float4 kv = krow[d4];
                float4 qv = qrow[d4];
                acc = fmaf(kv.x, qv.x, acc);
                acc = fmaf(kv.y, qv.y, acc);
                acc = fmaf(kv.z, qv.z, acc);
                acc = fmaf(kv.w, qv.w, acc);
            }
            sc[r * SC_STRIDE + k] = acc * SCALE_;
        }
    }
    __syncthreads();

    // Softmax: 16 threads per row.
    {
        const int r = tid >> 4;
        const int o = tid & 15;
        float* row = sc + r * SC_STRIDE;
        float m = -1e30f;
        for (int k = o; k < S_; k += 16) m = fmaxf(m, row[k]);
        #pragma unroll
        for (int msk = 8; msk; msk >>= 1) m = fmaxf(m, __shfl_xor_sync(~0u, m, msk));
        float sum = 0.f;
        for (int k = o; k < S_; k += 16) {
            float pv = __expf(row[k] - m);
            row[k] = pv;
            sum += pv;
        }
        #pragma unroll
        for (int msk = 8; msk; msk >>= 1) sum += __shfl_xor_sync(~0u, sum, msk);
        if (o == 0) s_inv[r] = 1.0f / sum;
    }
    __syncthreads();

    // PV pass: thread owns 4 dims (float4) x 4 rows.
    {
        const int d4 = (tid & 63) << 2;
        const int rg = tid >> 6;  // 0..3, rows rg*4 .. rg*4+3
        float4 a0 = make_float4(0, 0, 0, 0), a1 = a0, a2 = a0, a3 = a0;
        const float* vbase = batch_base + (NH_ + NKV_) * HD_ + kvh * HD_ + d4;
        const float* prow = sc + (rg * 4) * SC_STRIDE;

        #pragma unroll 2
        for (int k = 0; k < S_; k++) {
            float4 v = *(const float4*)(vbase + (size_t)k * F_);
            float p0 = prow[k];
            float p1 = prow[SC_STRIDE + k];
            float p2 = prow[2 * SC_STRIDE + k];
            float p3 = prow[3 * SC_STRIDE + k];
            a0.x = fmaf(p0, v.x, a0.x); a0.y = fmaf(p0, v.y, a0.y);
            a0.z = fmaf(p0, v.z, a0.z); a0.w = fmaf(p0, v.w, a0.w);
            a1.x = fmaf(p1, v.x, a1.x); a1.y = fmaf(p1, v.y, a1.y);
            a1.z = fmaf(p1, v.z, a1.z); a1.w = fmaf(p1, v.w, a1.w);
            a2.x = fmaf(p2, v.x, a2.x); a2.y = fmaf(p2, v.y, a2.y);
            a2.z = fmaf(p2, v.z, a2.z); a2.w = fmaf(p2, v.w, a2.w);
            a3.x = fmaf(p3, v.x, a3.x); a3.y = fmaf(p3, v.y, a3.y);
            a3.z = fmaf(p3, v.z, a3.z); a3.w = fmaf(p3, v.w, a3.w);
        }

        float4 accs[4] = {a0, a1, a2, a3};
        #pragma unroll
        for (int rr = 0; rr < 4; rr++) {
            float inv = s_inv[rg * 4 + rr];
            float4 o = accs[rr];
            o.x *= inv; o.y *= inv; o.z *= inv; o.w *= inv;
            *(float4*)(aout + (size_t)(b * S_ + q0 + rg * 4 + rr) * (NH_ * HD_)
                       + h * HD_ + d4) = o;
        }
    }
}

// ---------------------------------------------------------------------------
// Launch
// ---------------------------------------------------------------------------
extern "C" void kernel_launch(void* const* d_in, const int* in_sizes, int n_in,
                              void* d_out, int out_size)
{
    const float* hidden = (const float*)d_in[0];
    const float* cosb   = (const float*)d_in[1];
    const float* sinb   = (const float*)d_in[2];
    const float* w_qkv  = (const float*)d_in[3];
    const float* w_o    = (const float*)d_in[4];
    const float* q_w    = (const float*)d_in[5];
    const float* k_w    = (const float*)d_in[6];
    float* out = (float*)d_out;

    float* qkv; cudaGetSymbolAddress((void**)&qkv, g_qkv);
    float* ao;  cudaGetSymbolAddress((void**)&ao,  g_ao);

    cudaFuncSetAttribute(attn_kernel, cudaFuncAttributeMaxDynamicSharedMemorySize,
                         ATTN_SMEM_BYTES);

    // 1) QKV projection: [4096,2048] @ [2048,8192]
    {
        dim3 grid(F_ / BN, M1_ / BM);
        sgemm_kernel<<<grid, 256>>>(hidden, w_qkv, qkv, M1_, F_, HID_);
    }

    // 2) RMSNorm + RoPE on q,k heads
    norm_rope_kernel<<<M1_ * (NH_ + NKV_), 256>>>(qkv, cosb, sinb, q_w, k_w);

    // 3) Attention
    attn_kernel<<<B_ * NH_ * (S_ / BQ), 256, ATTN_SMEM_BYTES>>>(qkv, ao);

    // 4) Output projection: [4096,4096] @ [4096,2048]
    {
        dim3 grid(HID_ / BN, M1_ / BM);
        sgemm_kernel<<<grid, 256>>>(ao, w_o, out, M1_, HID_, NH_ * HD_);
    }
}

// round 3
// speedup vs baseline: 1.0312x; 1.0312x over previous
#include <cuda_runtime.h>
#include <cuda_bf16.h>
#include <math.h>

// Problem constants
#define B_   2
#define S_   2048
#define HID_ 2048
#define NH_  16
#define NKV_ 8
#define HD_  256
#define F_   8192      // (NH + 2*NKV) * HD
#define M1_  4096      // B*S
#define EPS_ 1e-6f
#define SCALE_ 0.0625f // 256^-0.5

// Scratch (device globals, no allocation)
__device__ float g_qkv[(size_t)M1_ * F_];        // qkv projection result
__device__ float g_ao [(size_t)M1_ * (NH_*HD_)]; // attention output

// ---------------------------------------------------------------------------
// Packed f32x2 helpers (Blackwell FFMA2 path)
// ---------------------------------------------------------------------------
__device__ __forceinline__ unsigned long long pk2(float x, float y) {
    unsigned long long r;
    asm("mov.b64 %0, {%1, %2};" : "=l"(r) : "f"(x), "f"(y));
    return r;
}
__device__ __forceinline__ void upk2(unsigned long long v, float& x, float& y) {
    asm("mov.b64 {%0, %1}, %2;" : "=f"(x), "=f"(y) : "l"(v));
}
__device__ __forceinline__ unsigned long long fma2(
    unsigned long long a, unsigned long long b, unsigned long long c) {
    unsigned long long d;
    asm("fma.rn.f32x2 %0, %1, %2, %3;" : "=l"(d) : "l"(a), "l"(b), "l"(c));
    return d;
}

// ---------------------------------------------------------------------------
// bf16x3 split tensor-core GEMM: C[M,N] = A[M,K] @ B[K,N], fp32 in/out.
// A,B row-major. M,N mult of 128, K mult of 32. 256 threads.
// Each fp32 split into bf16 hi+lo; C = Ah*Bh + Ah*Bl + Al*Bh via HMMA.
// ---------------------------------------------------------------------------
#define BM 128
#define BN 128
#define BK 32
#define BKP 40   // padded stride in bf16 elements (80B = 20 banks -> conflict-free)

#define MMA_BF16(c, a, b) \
    asm volatile("mma.sync.aligned.m16n8k16.row.col.f32.bf16.bf16.f32 " \
        "{%0,%1,%2,%3}, {%4,%5,%6,%7}, {%8,%9}, {%0,%1,%2,%3};" \
        : "+f"(c[0]), "+f"(c[1]), "+f"(c[2]), "+f"(c[3]) \
        : "r"(a[0]), "r"(a[1]), "r"(a[2]), "r"(a[3]), "r"(b[0]), "r"(b[1]))

__global__ __launch_bounds__(256) void mma_gemm_kernel(
    const float* __restrict__ A, const float* __restrict__ Bm,
    float* __restrict__ C, int M, int N, int K)
{
    __shared__ __nv_bfloat16 Ash[BM][BKP];
    __shared__ __nv_bfloat16 Asl[BM][BKP];
    __shared__ __nv_bfloat16 Bsh[BN][BKP];
    __shared__ __nv_bfloat16 Bsl[BN][BKP];

    const int tid  = threadIdx.x;
    const int brow = blockIdx.y * BM;
    const int bcol = blockIdx.x * BN;

    const int lane = tid & 31;
    const int wid  = tid >> 5;
    const int wm   = (wid >> 2) * 64;   // warp row offset: 0 or 64
    const int wn   = (wid & 3) * 32;    // warp col offset: 0,32,64,96
    const int grp  = lane >> 2;         // 0..7
    const int tig  = lane & 3;          // 0..3

    float acc[4][4][4];
    #pragma unroll
    for (int i = 0; i < 4; i++)
        #pragma unroll
        for (int j = 0; j < 4; j++)
            #pragma unroll
            for (int r = 0; r < 4; r++) acc[i][j][r] = 0.f;

    const int nchunks = K / BK;
    float4 rA[4], rB[4];

    // prologue: load chunk 0 into registers
    #pragma unroll
    for (int t = 0; t < 4; t++) {
        int ia = tid + t * 256;                 // 0..1023
        int ar = ia >> 3, ac4 = ia & 7;         // A: 128 rows x 8 float4
        rA[t] = *(const float4*)&A[(size_t)(brow + ar) * K + ac4 * 4];
        int ib = tid + t * 256;
        int bk = ib >> 5, bn4 = ib & 31;        // B: 32 rows x 32 float4
        rB[t] = *(const float4*)&Bm[(size_t)bk * N + bcol + bn4 * 4];
    }

    for (int chunk = 0; chunk < nchunks; chunk++) {
        // stage registers -> smem with hi/lo split
        #pragma unroll
        for (int t = 0; t < 4; t++) {
            int ia = tid + t * 256;
            int ar = ia >> 3, ac = (ia & 7) * 4;
            float v[4] = {rA[t].x, rA[t].y, rA[t].z, rA[t].w};
            #pragma unroll
            for (int j = 0; j < 4; j++) {
                __nv_bfloat16 h = __float2bfloat16(v[j]);
                Ash[ar][ac + j] = h;
                Asl[ar][ac + j] = __float2bfloat16(v[j] - __bfloat162float(h));
            }
            int ib = tid + t * 256;
            int bk = ib >> 5, bn = (ib & 31) * 4;
            float w[4] = {rB[t].x, rB[t].y, rB[t].z, rB[t].w};
            #pragma unroll
            for (int j = 0; j < 4; j++) {
                __nv_bfloat16 h = __float2bfloat16(w[j]);
                Bsh[bn + j][bk] = h;
                Bsl[bn + j][bk] = __float2bfloat16(w[j] - __bfloat162float(h));
            }
        }
        __syncthreads();

        // prefetch next chunk
        if (chunk + 1 < nchunks) {
            int k0 = (chunk + 1) * BK;
            #pragma unroll
            for (int t = 0; t < 4; t++) {
                int ia = tid + t * 256;
                int ar = ia >> 3, ac4 = ia & 7;
                rA[t] = *(const float4*)&A[(size_t)(brow + ar) * K + k0 + ac4 * 4];
                int ib = tid + t * 256;
                int bk = ib >> 5, bn4 = ib & 31;
                rB[t] = *(const float4*)&Bm[(size_t)(k0 + bk) * N + bcol + bn4 * 4];
            }
        }

        // compute: 2 k-steps of 16
        #pragma unroll
        for (int ks = 0; ks < 2; ks++) {
            const int kb = ks * 16 + tig * 2;
            unsigned ah[4][4], al[4][4], bh[4][2], bl[4][2];
            #pragma unroll
            for (int i = 0; i < 4; i++) {
                int r0 = wm + i * 16 + grp;
                ah[i][0] = *(const unsigned*)&Ash[r0][kb];
                ah[i][1] = *(const unsigned*)&Ash[r0 + 8][kb];
                ah[i][2] = *(const unsigned*)&Ash[r0][kb + 8];
                ah[i][3] = *(const unsigned*)&Ash[r0 + 8][kb + 8];
                al[i][0] = *(const unsigned*)&Asl[r0][kb];
                al[i][1] = *(const unsigned*)&Asl[r0 + 8][kb];
                al[i][2] = *(const unsigned*)&Asl[r0][kb + 8];
                al[i][3] = *(const unsigned*)&Asl[r0 + 8][kb + 8];
            }
            #pragma unroll
            for (int j = 0; j < 4; j++) {
                int n0 = wn + j * 8 + grp;
                bh[j][0] = *(const unsigned*)&Bsh[n0][kb];
                bh[j][1] = *(const unsigned*)&Bsh[n0][kb + 8];
                bl[j][0] = *(const unsigned*)&Bsl[n0][kb];
                bl[j][1] = *(const unsigned*)&Bsl[n0][kb + 8];
            }
            #pragma unroll
            for (int i = 0; i < 4; i++)
                #pragma unroll
                for (int j = 0; j < 4; j++) {
                    MMA_BF16(acc[i][j], ah[i], bh[j]);
                    MMA_BF16(acc[i][j], ah[i], bl[j]);
                    MMA_BF16(acc[i][j], al[i], bh[j]);
                }
        }
        __syncthreads();
    }

    // store C
    #pragma unroll
    for (int i = 0; i < 4; i++) {
        #pragma unroll
        for (int j = 0; j < 4; j++) {
            int row = brow + wm + i * 16 + grp;
            int col = bcol + wn + j * 8 + tig * 2;
            float* c0 = &C[(size_t)row * N + col];
            c0[0] = acc[i][j][0];
            c0[1] = acc[i][j][1];
            float* c1 = c0 + (size_t)8 * N;
            c1[0] = acc[i][j][2];
            c1[1] = acc[i][j][3];
        }
    }
}

// ---------------------------------------------------------------------------
// RMSNorm + RoPE, in-place on q and k heads of g_qkv.
// ---------------------------------------------------------------------------
__global__ __launch_bounds__(256) void norm_rope_kernel(
    float* __restrict__ qkv, const float* __restrict__ cosb,
    const float* __restrict__ sinb, const float* __restrict__ qw,
    const float* __restrict__ kw)
{
    const int blk = blockIdx.x;
    const int h24 = blk % (NH_ + NKV_);
    const int bs  = blk / (NH_ + NKV_);
    const int tid = threadIdx.x;

    const bool isq = (h24 < NH_);
    const int off  = isq ? h24 * HD_ : NH_ * HD_ + (h24 - NH_) * HD_;
    float* p = qkv + (size_t)bs * F_ + off;

    float x = p[tid];
    float ss = x * x;
    #pragma unroll
    for (int m = 16; m; m >>= 1) ss += __shfl_xor_sync(~0u, ss, m);

    __shared__ float warpsum[8];
    __shared__ float xn_s[HD_];
    if ((tid & 31) == 0) warpsum[tid >> 5] = ss;
    __syncthreads();
    float tot = warpsum[0] + warpsum[1] + warpsum[2] + warpsum[3]
              + warpsum[4] + warpsum[5] + warpsum[6] + warpsum[7];

    float inv = rsqrtf(tot * (1.0f / HD_) + EPS_);
    const float* w = isq ? qw : kw;
    float xn = x * inv * (1.0f + w[tid]);
    xn_s[tid] = xn;
    __syncthreads();

    float rot = (tid < HD_ / 2) ? -xn_s[tid + HD_ / 2] : xn_s[tid - HD_ / 2];
    float c = cosb[(size_t)bs * HD_ + tid];
    float s = sinb[(size_t)bs * HD_ + tid];
    p[tid] = xn * c + rot * s;
}

// ---------------------------------------------------------------------------
// Attention: one block per (b, h, 16-query tile). Two-pass with packed f32x2.
// ---------------------------------------------------------------------------
#define BQ 16
#define QS_STRIDE 260
#define SC_STRIDE 2049
#define ATTN_SMEM_BYTES ((BQ * QS_STRIDE + BQ * SC_STRIDE) * 4)

__global__ __launch_bounds__(256) void attn_kernel(
    const float* __restrict__ qkv, float* __restrict__ aout)
{
    extern __shared__ float smem[];
    float* qs = smem;                   // [BQ][QS_STRIDE]
    float* sc = smem + BQ * QS_STRIDE;  // [BQ][SC_STRIDE]
    __shared__ float s_inv[BQ];

    const int tid  = threadIdx.x;
    const int blk  = blockIdx.x;
    const int qt   = blk % (S_ / BQ);
    const int bh   = blk / (S_ / BQ);
    const int h    = bh % NH_;
    const int b    = bh / NH_;
    const int kvh  = h / (NH_ / NKV_);
    const int q0   = qt * BQ;

    const float* batch_base = qkv + (size_t)b * S_ * F_;
    const float* qbase = batch_base + (size_t)q0 * F_ + h * HD_;

    for (int i = tid; i < BQ * HD_; i += 256) {
        int rr = i >> 8, dd = i & 255;
        qs[rr * QS_STRIDE + dd] = qbase[(size_t)rr * F_ + dd];
    }
    __syncthreads();

    // Score pass (packed f32x2 FMA)
    {
        const int lane = tid & 31;
        const int warp = tid >> 5;
        const int r  = lane & 15;
        const int kk = lane >> 4;
        const float* kbase = batch_base + NH_ * HD_ + kvh * HD_;
        const float4* qrow = (const float4*)(qs + r * QS_STRIDE);

        for (int kp = warp; kp < S_ / 2; kp += 8) {
            const int k = kp * 2 + kk;
            const float4* krow = (const float4*)(kbase + (size_t)k * F_);
            unsigned long long acc01 = pk2(0.f, 0.f);
            unsigned long long acc23 = pk2(0.f, 0.f);
            #pragma unroll 8
            for (int d4 = 0; d4 < HD_ / 4; d4++) {
                float4 kv = krow[d4];
                float4 qv = qrow[d4];
                acc01 = fma2(pk2(kv.x, kv.y), pk2(qv.x, qv.y), acc01);
                acc23 = fma2(pk2(kv.z, kv.w), pk2(qv.z, qv.w), acc23);
            }
            float s0, s1, s2, s3;
            upk2(acc01, s0, s1);
            upk2(acc23, s2, s3);
            sc[r * SC_STRIDE + k] = (s0 + s1 + s2 + s3) * SCALE_;
        }
    }
    __syncthreads();

    // Softmax
    {
        const int r = tid >> 4;
        const int o = tid & 15;
        float* row = sc + r * SC_STRIDE;
        float m = -1e30f;
        for (int k = o; k < S_; k += 16) m = fmaxf(m, row[k]);
        #pragma unroll
        for (int msk = 8; msk; msk >>= 1) m = fmaxf(m, __shfl_xor_sync(~0u, m, msk));
        float sum = 0.f;
        for (int k = o; k < S_; k += 16) {
            float pv = __expf(row[k] - m);
            row[k] = pv;
            sum += pv;
        }
        #pragma unroll
        for (int msk = 8; msk; msk >>= 1) sum += __shfl_xor_sync(~0u, sum, msk);
        if (o == 0) s_inv[r] = 1.0f / sum;
    }
    __syncthreads();

    // PV pass (packed f32x2 FMA)
    {
        const int d4 = (tid & 63) << 2;
        const int rg = tid >> 6;
        unsigned long long a[4][2];
        #pragma unroll
        for (int r = 0; r < 4; r++) {
            a[r][0] = pk2(0.f, 0.f);
            a[r][1] = pk2(0.f, 0.f);
        }
        const float* vbase = batch_base + (NH_ + NKV_) * HD_ + kvh * HD_ + d4;
        const float* prow = sc + (rg * 4) * SC_STRIDE;

        #pragma unroll 2
        for (int k = 0; k < S_; k++) {
            float4 v = *(const float4*)(vbase + (size_t)k * F_);
            unsigned long long vxy = pk2(v.x, v.y);
            unsigned long long vzw = pk2(v.z, v.w);
            #pragma unroll
            for (int r = 0; r < 4; r++) {
                float p = prow[(size_t)r * SC_STRIDE + k];
                unsigned long long pp = pk2(p, p);
                a[r][0] = fma2(pp, vxy, a[r][0]);
                a[r][1] = fma2(pp, vzw, a[r][1]);
            }
        }

        #pragma unroll
        for (int r = 0; r < 4; r++) {
            float inv = s_inv[rg * 4 + r];
            float o0, o1, o2, o3;
            upk2(a[r][0], o0, o1);
            upk2(a[r][1], o2, o3);
            float4 o = make_float4(o0 * inv, o1 * inv, o2 * inv, o3 * inv);
            *(float4*)(aout + (size_t)(b * S_ + q0 + rg * 4 + r) * (NH_ * HD_)
                       + h * HD_ + d4) = o;
        }
    }
}

// ---------------------------------------------------------------------------
// Launch
// ---------------------------------------------------------------------------
extern "C" void kernel_launch(void* const* d_in, const int* in_sizes, int n_in,
                              void* d_out, int out_size)
{
    const float* hidden = (const float*)d_in[0];
    const float* cosb   = (const float*)d_in[1];
    const float* sinb   = (const float*)d_in[2];
    const float* w_qkv  = (const float*)d_in[3];
    const float* w_o    = (const float*)d_in[4];
    const float* q_w    = (const float*)d_in[5];
    const float* k_w    = (const float*)d_in[6];
    float* out = (float*)d_out;

    float* qkv; cudaGetSymbolAddress((void**)&qkv, g_qkv);
    float* ao;  cudaGetSymbolAddress((void**)&ao,  g_ao);

    cudaFuncSetAttribute(attn_kernel, cudaFuncAttributeMaxDynamicSharedMemorySize,
                         ATTN_SMEM_BYTES);

    // 1) QKV projection: [4096,2048] @ [2048,8192]
    {
        dim3 grid(F_ / BN, M1_ / BM);
        mma_gemm_kernel<<<grid, 256>>>(hidden, w_qkv, qkv, M1_, F_, HID_);
    }

    // 2) RMSNorm + RoPE
    norm_rope_kernel<<<M1_ * (NH_ + NKV_), 256>>>(qkv, cosb, sinb, q_w, k_w);

    // 3) Attention
    attn_kernel<<<B_ * NH_ * (S_ / BQ), 256, ATTN_SMEM_BYTES>>>(qkv, ao);

    // 4) Output projection: [4096,4096] @ [4096,2048]
    {
        dim3 grid(HID_ / BN, M1_ / BM);
        mma_gemm_kernel<<<grid, 256>>>(ao, w_o, out, M1_, HID_, NH_ * HD_);
    }
}

// round 4
// speedup vs baseline: 4.9077x; 4.7594x over previous
#include <cuda_runtime.h>
#include <cuda_bf16.h>
#include <math.h>
#include <stdint.h>

// Problem constants
#define B_   2
#define S_   2048
#define HID_ 2048
#define NH_  16
#define NKV_ 8
#define HD_  256
#define F_   8192      // (NH + 2*NKV) * HD
#define M1_  4096      // B*S
#define EPS_ 1e-6f
#define SCALE_ 0.0625f // 256^-0.5
#define LOG2E_ 1.4426950408889634f

// Scratch (device globals, no allocation)
__device__ float g_qkv[(size_t)M1_ * F_];          // qkv projection (fp32)
__device__ float g_ao [(size_t)M1_ * (NH_*HD_)];   // attention output (fp32)
__device__ __nv_bfloat16 g_h[(size_t)M1_ * F_];    // hi split (q scaled+roped, k roped, v)
__device__ __nv_bfloat16 g_l[(size_t)M1_ * F_];    // lo split

// ---------------------------------------------------------------------------
// helpers
// ---------------------------------------------------------------------------
__device__ __forceinline__ uint32_t s2u(const void* p) {
    return (uint32_t)__cvta_generic_to_shared(p);
}
__device__ __forceinline__ float ex2f(float x) {
    float y; asm("ex2.approx.f32 %0, %1;" : "=f"(y) : "f"(x)); return y;
}
__device__ __forceinline__ uint32_t pack_bf16(float lo, float hi) {
    uint32_t r;
    asm("cvt.rn.bf16x2.f32 %0, %1, %2;" : "=r"(r) : "f"(hi), "f"(lo));
    return r;
}
__device__ __forceinline__ float bf_round(float x) {
    return __bfloat162float(__float2bfloat16(x));
}

#define MMA_BF16(c, a, b) \
    asm volatile("mma.sync.aligned.m16n8k16.row.col.f32.bf16.bf16.f32 " \
        "{%0,%1,%2,%3}, {%4,%5,%6,%7}, {%8,%9}, {%0,%1,%2,%3};" \
        : "+f"((c)[0]), "+f"((c)[1]), "+f"((c)[2]), "+f"((c)[3]) \
        : "r"((a)[0]), "r"((a)[1]), "r"((a)[2]), "r"((a)[3]), \
          "r"((b)[0]), "r"((b)[1]))

#define LDSM_X4(r0, r1, r2, r3, addr) \
    asm volatile("ldmatrix.sync.aligned.m8n8.x4.shared.b16 {%0,%1,%2,%3}, [%4];" \
        : "=r"(r0), "=r"(r1), "=r"(r2), "=r"(r3) : "r"(addr))

#define LDSM_X2T(r0, r1, addr) \
    asm volatile("ldmatrix.sync.aligned.m8n8.x2.trans.shared.b16 {%0,%1}, [%2];" \
        : "=r"(r0), "=r"(r1) : "r"(addr))

// ---------------------------------------------------------------------------
// bf16x3 split tensor-core GEMM (unchanged from R3)
// ---------------------------------------------------------------------------
#define BM 128
#define BN 128
#define BK 32
#define BKP 40

__global__ __launch_bounds__(256) void mma_gemm_kernel(
    const float* __restrict__ A, const float* __restrict__ Bm,
    float* __restrict__ C, int M, int N, int K)
{
    __shared__ __nv_bfloat16 Ash[BM][BKP];
    __shared__ __nv_bfloat16 Asl[BM][BKP];
    __shared__ __nv_bfloat16 Bsh[BN][BKP];
    __shared__ __nv_bfloat16 Bsl[BN][BKP];

    const int tid  = threadIdx.x;
    const int brow = blockIdx.y * BM;
    const int bcol = blockIdx.x * BN;

    const int lane = tid & 31;
    const int wid  = tid >> 5;
    const int wm   = (wid >> 2) * 64;
    const int wn   = (wid & 3) * 32;
    const int grp  = lane >> 2;
    const int tig  = lane & 3;

    float acc[4][4][4];
    #pragma unroll
    for (int i = 0; i < 4; i++)
        #pragma unroll
        for (int j = 0; j < 4; j++)
            #pragma unroll
            for (int r = 0; r < 4; r++) acc[i][j][r] = 0.f;

    const int nchunks = K / BK;
    float4 rA[4], rB[4];

    #pragma unroll
    for (int t = 0; t < 4; t++) {
        int ia = tid + t * 256;
        int ar = ia >> 3, ac4 = ia & 7;
        rA[t] = *(const float4*)&A[(size_t)(brow + ar) * K + ac4 * 4];
        int ib = tid + t * 256;
        int bk = ib >> 5, bn4 = ib & 31;
        rB[t] = *(const float4*)&Bm[(size_t)bk * N + bcol + bn4 * 4];
    }

    for (int chunk = 0; chunk < nchunks; chunk++) {
        #pragma unroll
        for (int t = 0; t < 4; t++) {
            int ia = tid + t * 256;
            int ar = ia >> 3, ac = (ia & 7) * 4;
            float v[4] = {rA[t].x, rA[t].y, rA[t].z, rA[t].w};
            #pragma unroll
            for (int j = 0; j < 4; j++) {
                __nv_bfloat16 hh = __float2bfloat16(v[j]);
                Ash[ar][ac + j] = hh;
                Asl[ar][ac + j] = __float2bfloat16(v[j] - __bfloat162float(hh));
            }
            int ib = tid + t * 256;
            int bk = ib >> 5, bn = (ib & 31) * 4;
            float w[4] = {rB[t].x, rB[t].y, rB[t].z, rB[t].w};
            #pragma unroll
            for (int j = 0; j < 4; j++) {
                __nv_bfloat16 hh = __float2bfloat16(w[j]);
                Bsh[bn + j][bk] = hh;
                Bsl[bn + j][bk] = __float2bfloat16(w[j] - __bfloat162float(hh));
            }
        }
        __syncthreads();

        if (chunk + 1 < nchunks) {
            int k0 = (chunk + 1) * BK;
            #pragma unroll
            for (int t = 0; t < 4; t++) {
                int ia = tid + t * 256;
                int ar = ia >> 3, ac4 = ia & 7;
                rA[t] = *(const float4*)&A[(size_t)(brow + ar) * K + k0 + ac4 * 4];
                int ib = tid + t * 256;
                int bk = ib >> 5, bn4 = ib & 31;
                rB[t] = *(const float4*)&Bm[(size_t)(k0 + bk) * N + bcol + bn4 * 4];
            }
        }

        #pragma unroll
        for (int ks = 0; ks < 2; ks++) {
            const int kb = ks * 16 + tig * 2;
            unsigned ah[4][4], al[4][4], bh[4][2], bl[4][2];
            #pragma unroll
            for (int i = 0; i < 4; i++) {
                int r0 = wm + i * 16 + grp;
                ah[i][0] = *(const unsigned*)&Ash[r0][kb];
                ah[i][1] = *(const unsigned*)&Ash[r0 + 8][kb];
                ah[i][2] = *(const unsigned*)&Ash[r0][kb + 8];
                ah[i][3] = *(const unsigned*)&Ash[r0 + 8][kb + 8];
                al[i][0] = *(const unsigned*)&Asl[r0][kb];
                al[i][1] = *(const unsigned*)&Asl[r0 + 8][kb];
                al[i][2] = *(const unsigned*)&Asl[r0][kb + 8];
                al[i][3] = *(const unsigned*)&Asl[r0 + 8][kb + 8];
            }
            #pragma unroll
            for (int j = 0; j < 4; j++) {
                int n0 = wn + j * 8 + grp;
                bh[j][0] = *(const unsigned*)&Bsh[n0][kb];
                bh[j][1] = *(const unsigned*)&Bsh[n0][kb + 8];
                bl[j][0] = *(const unsigned*)&Bsl[n0][kb];
                bl[j][1] = *(const unsigned*)&Bsl[n0][kb + 8];
            }
            #pragma unroll
            for (int i = 0; i < 4; i++)
                #pragma unroll
                for (int j = 0; j < 4; j++) {
                    MMA_BF16(acc[i][j], ah[i], bh[j]);
                    MMA_BF16(acc[i][j], ah[i], bl[j]);
                    MMA_BF16(acc[i][j], al[i], bh[j]);
                }
        }
        __syncthreads();
    }

    #pragma unroll
    for (int i = 0; i < 4; i++) {
        #pragma unroll
        for (int j = 0; j < 4; j++) {
            int row = brow + wm + i * 16 + grp;
            int col = bcol + wn + j * 8 + tig * 2;
            float* c0 = &C[(size_t)row * N + col];
            c0[0] = acc[i][j][0];
            c0[1] = acc[i][j][1];
            float* c1 = c0 + (size_t)8 * N;
            c1[0] = acc[i][j][2];
            c1[1] = acc[i][j][3];
        }
    }
}

// ---------------------------------------------------------------------------
// Split kernel: RMSNorm+RoPE for q,k heads (q pre-scaled by SCALE), v pass-
// through; writes bf16 hi/lo split to g_h/g_l. One block per (token, head32).
// ---------------------------------------------------------------------------
__global__ __launch_bounds__(256) void split_kernel(
    const float* __restrict__ qkv, const float* __restrict__ cosb,
    const float* __restrict__ sinb, const float* __restrict__ qw,
    const float* __restrict__ kw, __nv_bfloat16* __restrict__ gh,
    __nv_bfloat16* __restrict__ gl)
{
    const int blk = blockIdx.x;
    const int h32 = blk & 31;
    const int bs  = blk >> 5;
    const int tid = threadIdx.x;

    const size_t base = (size_t)bs * F_ + h32 * HD_;
    float x = qkv[base + tid];
    float val;

    if (h32 < NH_ + NKV_) {
        // RMSNorm
        float ss = x * x;
        #pragma unroll
        for (int m = 16; m; m >>= 1) ss += __shfl_xor_sync(~0u, ss, m);
        __shared__ float warpsum[8];
        __shared__ float xn_s[HD_];
        if ((tid & 31) == 0) warpsum[tid >> 5] = ss;
        __syncthreads();
        float tot = warpsum[0] + warpsum[1] + warpsum[2] + warpsum[3]
                  + warpsum[4] + warpsum[5] + warpsum[6] + warpsum[7];
        float inv = rsqrtf(tot * (1.0f / HD_) + EPS_);
        const float* w = (h32 < NH_) ? qw : kw;
        float xn = x * inv * (1.0f + w[tid]);
        xn_s[tid] = xn;
        __syncthreads();
        float rot = (tid < HD_ / 2) ? -xn_s[tid + HD_ / 2] : xn_s[tid - HD_ / 2];
        float c = cosb[(size_t)bs * HD_ + tid];
        float s = sinb[(size_t)bs * HD_ + tid];
        val = xn * c + rot * s;
        if (h32 < NH_) val *= SCALE_;
    } else {
        val = x;
    }

    __nv_bfloat16 hi = __float2bfloat16(val);
    gh[base + tid] = hi;
    gl[base + tid] = __float2bfloat16(val - __bfloat162float(hi));
}

// ---------------------------------------------------------------------------
// MMA flash attention. Block = (b, h, 128-query tile), 8 warps x 16 rows.
// K/V streamed in 32-key tiles. bf16x3 for QK^T and PV; fp32 online softmax.
// ---------------------------------------------------------------------------
#define QSTR 264   // smem row stride in bf16 elems (conflict-free for ldmatrix)
#define TK 32
#define FATTN_SMEM ((128 * QSTR * 2 + TK * QSTR * 4) * 2)  // bytes

__global__ __launch_bounds__(256, 1) void fattn_kernel(
    const __nv_bfloat16* __restrict__ gh, const __nv_bfloat16* __restrict__ gl,
    float* __restrict__ aout)
{
    extern __shared__ __nv_bfloat16 sm[];
    __nv_bfloat16* QH = sm;
    __nv_bfloat16* QL = QH + 128 * QSTR;
    __nv_bfloat16* KH = QL + 128 * QSTR;
    __nv_bfloat16* KL = KH + TK * QSTR;
    __nv_bfloat16* VH = KL + TK * QSTR;
    __nv_bfloat16* VL = VH + TK * QSTR;

    const int tid = threadIdx.x;
    const int w = tid >> 5;
    const int l = tid & 31;

    const int qt = blockIdx.x & 15;
    const int h  = (blockIdx.x >> 4) & 15;
    const int b  = blockIdx.x >> 8;
    const int kvh = h >> 1;
    const int q0 = qt * 128;

    const size_t koff = (size_t)NH_ * HD_ + kvh * HD_;   // 4096 + kvh*256
    const size_t voff = (size_t)(NH_ + NKV_) * HD_ + kvh * HD_;

    // Load Q tile (hi+lo)
    for (int i = tid; i < 128 * 32; i += 256) {
        int r = i >> 5, c = i & 31;
        size_t src = ((size_t)(b * S_ + q0 + r)) * F_ + h * HD_ + c * 8;
        int dst = r * QSTR + c * 8;
        *(uint4*)(QH + dst) = *(const uint4*)(gh + src);
        *(uint4*)(QL + dst) = *(const uint4*)(gl + src);
    }

    float o[32][4];
    #pragma unroll
    for (int nt = 0; nt < 32; nt++)
        #pragma unroll
        for (int j = 0; j < 4; j++) o[nt][j] = 0.f;

    float m_lo = -1e30f, m_hi = -1e30f, l_lo = 0.f, l_hi = 0.f;

    const uint32_t qh_b = s2u(QH), ql_b = s2u(QL);
    const uint32_t kh_b = s2u(KH), kl_b = s2u(KL);
    const uint32_t vh_b = s2u(VH), vl_b = s2u(VL);

    // per-lane fragment offsets
    const int qrow  = 16 * w + (l & 15);
    const int qcol8 = (l >> 4) << 3;
    const int krow  = (l & 7) + ((l >> 4) & 1) * 8;
    const int kcol8 = ((l >> 3) & 1) << 3;
    const int vrow  = l & 15;

    for (int kt = 0; kt < S_ / TK; kt++) {
        __syncthreads();
        for (int i = tid; i < TK * 32; i += 256) {
            int r = i >> 5, c = i & 31;
            size_t base = ((size_t)(b * S_ + kt * TK + r)) * F_;
            int dst = r * QSTR + c * 8;
            *(uint4*)(KH + dst) = *(const uint4*)(gh + base + koff + c * 8);
            *(uint4*)(KL + dst) = *(const uint4*)(gl + base + koff + c * 8);
            *(uint4*)(VH + dst) = *(const uint4*)(gh + base + voff + c * 8);
            *(uint4*)(VL + dst) = *(const uint4*)(gl + base + voff + c * 8);
        }
        __syncthreads();

        // ---- S = Q K^T (bf16x3) ----
        float sA[4][4];
        #pragma unroll
        for (int nt = 0; nt < 4; nt++)
            #pragma unroll
            for (int j = 0; j < 4; j++) sA[nt][j] = 0.f;

        #pragma unroll
        for (int ks = 0; ks < 16; ks++) {
            uint32_t ah[4], al[4];
            uint32_t qoff = (uint32_t)(qrow * QSTR + ks * 16 + qcol8) * 2;
            LDSM_X4(ah[0], ah[1], ah[2], ah[3], qh_b + qoff);
            LDSM_X4(al[0], al[1], al[2], al[3], ql_b + qoff);
            #pragma unroll
            for (int ntp = 0; ntp < 2; ntp++) {
                uint32_t bh[4], bl[4];
                uint32_t kofs = (uint32_t)((16 * ntp + krow) * QSTR + ks * 16 + kcol8) * 2;
                LDSM_X4(bh[0], bh[1], bh[2], bh[3], kh_b + kofs);
                LDSM_X4(bl[0], bl[1], bl[2], bl[3], kl_b + kofs);
                MMA_BF16(sA[2 * ntp],     ah, bh);
                MMA_BF16(sA[2 * ntp],     ah, bl);
                MMA_BF16(sA[2 * ntp],     al, bh);
                MMA_BF16(sA[2 * ntp + 1], ah, bh + 2);
                MMA_BF16(sA[2 * ntp + 1], ah, bl + 2);
                MMA_BF16(sA[2 * ntp + 1], al, bh + 2);
            }
        }

        // ---- online softmax update ----
        float tmax_lo = sA[0][0], tmax_hi = sA[0][2];
        #pragma unroll
        for (int nt = 0; nt < 4; nt++) {
            tmax_lo = fmaxf(tmax_lo, fmaxf(sA[nt][0], sA[nt][1]));
            tmax_hi = fmaxf(tmax_hi, fmaxf(sA[nt][2], sA[nt][3]));
        }
        tmax_lo = fmaxf(tmax_lo, __shfl_xor_sync(~0u, tmax_lo, 1));
        tmax_lo = fmaxf(tmax_lo, __shfl_xor_sync(~0u, tmax_lo, 2));
        tmax_hi = fmaxf(tmax_hi, __shfl_xor_sync(~0u, tmax_hi, 1));
        tmax_hi = fmaxf(tmax_hi, __shfl_xor_sync(~0u, tmax_hi, 2));

        float mn_lo = fmaxf(m_lo, tmax_lo);
        float mn_hi = fmaxf(m_hi, tmax_hi);
        float sc_lo = ex2f((m_lo - mn_lo) * LOG2E_);
        float sc_hi = ex2f((m_hi - mn_hi) * LOG2E_);
        m_lo = mn_lo; m_hi = mn_hi;

        float rs_lo = 0.f, rs_hi = 0.f;
        #pragma unroll
        for (int nt = 0; nt < 4; nt++) {
            sA[nt][0] = ex2f((sA[nt][0] - m_lo) * LOG2E_);
            sA[nt][1] = ex2f((sA[nt][1] - m_lo) * LOG2E_);
            sA[nt][2] = ex2f((sA[nt][2] - m_hi) * LOG2E_);
            sA[nt][3] = ex2f((sA[nt][3] - m_hi) * LOG2E_);
            rs_lo += sA[nt][0] + sA[nt][1];
            rs_hi += sA[nt][2] + sA[nt][3];
        }
        rs_lo += __shfl_xor_sync(~0u, rs_lo, 1);
        rs_lo += __shfl_xor_sync(~0u, rs_lo, 2);
        rs_hi += __shfl_xor_sync(~0u, rs_hi, 1);
        rs_hi += __shfl_xor_sync(~0u, rs_hi, 2);
        l_lo = l_lo * sc_lo + rs_lo;
        l_hi = l_hi * sc_hi + rs_hi;

        #pragma unroll
        for (int nt = 0; nt < 32; nt++) {
            o[nt][0] *= sc_lo; o[nt][1] *= sc_lo;
            o[nt][2] *= sc_hi; o[nt][3] *= sc_hi;
        }

        // ---- P fragments (hi/lo register split) ----
        uint32_t aPh[2][4], aPl[2][4];
        #pragma unroll
        for (int ksp = 0; ksp < 2; ksp++) {
            #pragma unroll
            for (int q = 0; q < 4; q++) {
                int nt = 2 * ksp + (q >> 1);
                int j0 = (q & 1) * 2;       // 0 or 2
                float p0 = sA[nt][j0], p1 = sA[nt][j0 + 1];
                float h0 = bf_round(p0), h1 = bf_round(p1);
                aPh[ksp][q] = pack_bf16(h0, h1);
                aPl[ksp][q] = pack_bf16(p0 - h0, p1 - h1);
            }
        }

        // ---- O += P V (bf16x3) ----
        #pragma unroll
        for (int ksp = 0; ksp < 2; ksp++) {
            #pragma unroll
            for (int nt = 0; nt < 32; nt++) {
                uint32_t vofs = (uint32_t)((16 * ksp + vrow) * QSTR + nt * 8) * 2;
                uint32_t bv[2], bw[2];
                LDSM_X2T(bv[0], bv[1], vh_b + vofs);
                LDSM_X2T(bw[0], bw[1], vl_b + vofs);
                MMA_BF16(o[nt], aPh[ksp], bv);
                MMA_BF16(o[nt], aPh[ksp], bw);
                MMA_BF16(o[nt], aPl[ksp], bv);
            }
        }
    }

    // epilogue: normalize and write
    float inv_lo = 1.0f / l_lo;
    float inv_hi = 1.0f / l_hi;
    const int row_lo = q0 + 16 * w + (l >> 2);
    const int col0 = h * HD_ + 2 * (l & 3);
    #pragma unroll
    for (int nt = 0; nt < 32; nt++) {
        float2 vlo = make_float2(o[nt][0] * inv_lo, o[nt][1] * inv_lo);
        float2 vhi = make_float2(o[nt][2] * inv_hi, o[nt][3] * inv_hi);
        *(float2*)(aout + (size_t)(b * S_ + row_lo)     * (NH_ * HD_) + col0 + nt * 8) = vlo;
        *(float2*)(aout + (size_t)(b * S_ + row_lo + 8) * (NH_ * HD_) + col0 + nt * 8) = vhi;
    }
}

// ---------------------------------------------------------------------------
// Launch
// ---------------------------------------------------------------------------
extern "C" void kernel_launch(void* const* d_in, const int* in_sizes, int n_in,
                              void* d_out, int out_size)
{
    const float* hidden = (const float*)d_in[0];
    const float* cosb   = (const float*)d_in[1];
    const float* sinb   = (const float*)d_in[2];
    const float* w_qkv  = (const float*)d_in[3];
    const float* w_o    = (const float*)d_in[4];
    const float* q_w    = (const float*)d_in[5];
    const float* k_w    = (const float*)d_in[6];
    float* out = (float*)d_out;

    float* qkv; cudaGetSymbolAddress((void**)&qkv, g_qkv);
    float* ao;  cudaGetSymbolAddress((void**)&ao,  g_ao);
    __nv_bfloat16* gh; cudaGetSymbolAddress((void**)&gh, g_h);
    __nv_bfloat16* gl; cudaGetSymbolAddress((void**)&gl, g_l);

    cudaFuncSetAttribute(fattn_kernel, cudaFuncAttributeMaxDynamicSharedMemorySize,
                         FATTN_SMEM);

    // 1) QKV projection
    {
        dim3 grid(F_ / BN, M1_ / BM);
        mma_gemm_kernel<<<grid, 256>>>(hidden, w_qkv, qkv, M1_, F_, HID_);
    }

    // 2) RMSNorm + RoPE + bf16 hi/lo split
    split_kernel<<<M1_ * 32, 256>>>(qkv, cosb, sinb, q_w, k_w, gh, gl);

    // 3) Flash attention (tensor cores)
    fattn_kernel<<<B_ * NH_ * (S_ / 128), 256, FATTN_SMEM>>>(gh, gl, ao);

    // 4) Output projection
    {
        dim3 grid(HID_ / BN, M1_ / BM);
        mma_gemm_kernel<<<grid, 256>>>(ao, w_o, out, M1_, HID_, NH_ * HD_);
    }
}

// round 5
// speedup vs baseline: 9.7096x; 1.9784x over previous
#include <cuda_runtime.h>
#include <cuda_bf16.h>
#include <math.h>
#include <stdint.h>

// Problem constants
#define B_   2
#define S_   2048
#define HID_ 2048
#define NH_  16
#define NKV_ 8
#define HD_  256
#define F_   8192      // (NH + 2*NKV) * HD
#define M1_  4096      // B*S
#define EPS_ 1e-6f
#define SCALE_ 0.0625f // 256^-0.5
#define LOG2E_ 1.4426950408889634f

// Scratch (device globals, no allocation)
__device__ float g_qkv[(size_t)M1_ * F_];          // qkv projection (fp32)
__device__ float g_ao [(size_t)M1_ * (NH_*HD_)];   // attention output (fp32)
__device__ __nv_bfloat16 g_h[(size_t)M1_ * F_];    // attn operands hi split
__device__ __nv_bfloat16 g_l[(size_t)M1_ * F_];    // attn operands lo split
// GEMM operand splits
__device__ __nv_bfloat16 g_hidh[(size_t)M1_ * HID_];
__device__ __nv_bfloat16 g_hidl[(size_t)M1_ * HID_];
__device__ __nv_bfloat16 g_wqh [(size_t)HID_ * F_];
__device__ __nv_bfloat16 g_wql [(size_t)HID_ * F_];
__device__ __nv_bfloat16 g_woh [(size_t)(NH_*HD_) * HID_];
__device__ __nv_bfloat16 g_wol [(size_t)(NH_*HD_) * HID_];
__device__ __nv_bfloat16 g_aoh [(size_t)M1_ * (NH_*HD_)];
__device__ __nv_bfloat16 g_aol [(size_t)M1_ * (NH_*HD_)];

// ---------------------------------------------------------------------------
// helpers
// ---------------------------------------------------------------------------
__device__ __forceinline__ uint32_t s2u(const void* p) {
    return (uint32_t)__cvta_generic_to_shared(p);
}
__device__ __forceinline__ float ex2f(float x) {
    float y; asm("ex2.approx.f32 %0, %1;" : "=f"(y) : "f"(x)); return y;
}
__device__ __forceinline__ uint32_t pack_bf16(float lo, float hi) {
    uint32_t r;
    asm("cvt.rn.bf16x2.f32 %0, %1, %2;" : "=r"(r) : "f"(hi), "f"(lo));
    return r;
}
__device__ __forceinline__ float bf_round(float x) {
    return __bfloat162float(__float2bfloat16(x));
}
__device__ __forceinline__ void cp16(uint32_t s, const void* g) {
    asm volatile("cp.async.cg.shared.global [%0], [%1], 16;" :: "r"(s), "l"(g));
}
#define CP_COMMIT asm volatile("cp.async.commit_group;")
#define CP_WAIT(n) asm volatile("cp.async.wait_group %0;" :: "n"(n))

#define MMA_BF16(c, a, b) \
    asm volatile("mma.sync.aligned.m16n8k16.row.col.f32.bf16.bf16.f32 " \
        "{%0,%1,%2,%3}, {%4,%5,%6,%7}, {%8,%9}, {%0,%1,%2,%3};" \
        : "+f"((c)[0]), "+f"((c)[1]), "+f"((c)[2]), "+f"((c)[3]) \
        : "r"((a)[0]), "r"((a)[1]), "r"((a)[2]), "r"((a)[3]), \
          "r"((b)[0]), "r"((b)[1]))

#define LDSM_X4(r0, r1, r2, r3, addr) \
    asm volatile("ldmatrix.sync.aligned.m8n8.x4.shared.b16 {%0,%1,%2,%3}, [%4];" \
        : "=r"(r0), "=r"(r1), "=r"(r2), "=r"(r3) : "r"(addr))

#define LDSM_X2T(r0, r1, addr) \
    asm volatile("ldmatrix.sync.aligned.m8n8.x2.trans.shared.b16 {%0,%1}, [%2];" \
        : "=r"(r0), "=r"(r1) : "r"(addr))

// ---------------------------------------------------------------------------
// Generic fp32 -> bf16 hi/lo split (memory-bound)
// ---------------------------------------------------------------------------
__global__ __launch_bounds__(256) void split_f32_kernel(
    const float* __restrict__ in, __nv_bfloat16* __restrict__ hi,
    __nv_bfloat16* __restrict__ lo, int n4)
{
    int i = blockIdx.x * 256 + threadIdx.x;
    if (i >= n4) return;
    float4 v = ((const float4*)in)[i];
    float h0 = bf_round(v.x), h1 = bf_round(v.y);
    float h2 = bf_round(v.z), h3 = bf_round(v.w);
    uint2 hp, lp;
    hp.x = pack_bf16(h0, h1);
    hp.y = pack_bf16(h2, h3);
    lp.x = pack_bf16(v.x - h0, v.y - h1);
    lp.y = pack_bf16(v.z - h2, v.w - h3);
    ((uint2*)hi)[i] = hp;
    ((uint2*)lo)[i] = lp;
}

// ---------------------------------------------------------------------------
// bf16x3 GEMM on pre-split operands. C[M,N] = A[M,K] @ B[K,N] (fp32 result).
// 128x128x32 tiles, cp.async double-buffer, ldmatrix fragments, 2 blocks/SM.
// ---------------------------------------------------------------------------
#define ASTR_B 80                    // A smem row stride (bytes): 64B data + 16 pad
#define BSTR_B 272                   // B smem row stride (bytes): 256B data + 16 pad
#define A_BYTES (128 * ASTR_B)       // 10240
#define B_BYTES (32 * BSTR_B)        // 8704
#define STAGE_BYTES (2 * A_BYTES + 2 * B_BYTES)  // 37888
#define GEMM_SMEM (2 * STAGE_BYTES)              // 75776

__global__ __launch_bounds__(256, 2) void gemm_bf16x3_kernel(
    const __nv_bfloat16* __restrict__ Ah, const __nv_bfloat16* __restrict__ Al,
    const __nv_bfloat16* __restrict__ Bh, const __nv_bfloat16* __restrict__ Bl,
    float* __restrict__ C, int M, int N, int K)
{
    extern __shared__ char gs[];
    const int tid  = threadIdx.x;
    const int lane = tid & 31;
    const int wid  = tid >> 5;
    const int brow = blockIdx.y * 128;
    const int bcol = blockIdx.x * 128;
    const int wm   = (wid >> 2) * 64;
    const int wn   = (wid & 3) * 32;

    const uint32_t gs_u = s2u(gs);
    const int nchunks = K / 32;

    // --- stage loader (8 cp.async per thread) ---
    auto load_stage = [&](int chunk, int s) {
        uint32_t sa = gs_u + s * STAGE_BYTES;
        uint32_t sb = sa + 2 * A_BYTES;
        int k0 = chunk * 32;
        #pragma unroll
        for (int t = 0; t < 2; t++) {
            int idx = tid + t * 256;
            int ar = idx >> 2, ac = idx & 3;
            size_t ga = (size_t)(brow + ar) * K + k0 + ac * 8;
            uint32_t sa_off = sa + ar * ASTR_B + ac * 16;
            cp16(sa_off,           Ah + ga);
            cp16(sa_off + A_BYTES, Al + ga);
            int br = idx >> 4, bc = idx & 15;
            size_t gb = (size_t)(k0 + br) * N + bcol + bc * 8;
            uint32_t sb_off = sb + br * BSTR_B + bc * 16;
            cp16(sb_off,           Bh + gb);
            cp16(sb_off + B_BYTES, Bl + gb);
        }
    };

    float acc[4][4][4];
    #pragma unroll
    for (int i = 0; i < 4; i++)
        #pragma unroll
        for (int j = 0; j < 4; j++)
            #pragma unroll
            for (int r = 0; r < 4; r++) acc[i][j][r] = 0.f;

    load_stage(0, 0);
    CP_COMMIT;

    for (int c = 0; c < nchunks; c++) {
        if (c + 1 < nchunks) {
            load_stage(c + 1, (c + 1) & 1);
            CP_COMMIT;
            CP_WAIT(1);
        } else {
            CP_WAIT(0);
        }
        __syncthreads();

        uint32_t sa = gs_u + (c & 1) * STAGE_BYTES;
        uint32_t sb = sa + 2 * A_BYTES;

        #pragma unroll
        for (int ks = 0; ks < 2; ks++) {
            const int kb = ks * 16;
            uint32_t bhf[4][2], blf[4][2];
            #pragma unroll
            for (int j = 0; j < 4; j++) {
                uint32_t ad = sb + (kb + (lane & 15)) * BSTR_B + (wn + j * 8) * 2;
                LDSM_X2T(bhf[j][0], bhf[j][1], ad);
                LDSM_X2T(blf[j][0], blf[j][1], ad + B_BYTES);
            }
            #pragma unroll
            for (int i = 0; i < 4; i++) {
                uint32_t ahf[4], alf[4];
                uint32_t ad = sa + (wm + i * 16 + (lane & 15)) * ASTR_B
                            + (kb + ((lane >> 4) << 3)) * 2;
                LDSM_X4(ahf[0], ahf[1], ahf[2], ahf[3], ad);
                LDSM_X4(alf[0], alf[1], alf[2], alf[3], ad + A_BYTES);
                #pragma unroll
                for (int j = 0; j < 4; j++) {
                    MMA_BF16(acc[i][j], ahf, bhf[j]);
                    MMA_BF16(acc[i][j], ahf, blf[j]);
                    MMA_BF16(acc[i][j], alf, bhf[j]);
                }
            }
        }
        __syncthreads();
    }

    // epilogue
    const int grp = lane >> 2;
    const int tig = lane & 3;
    #pragma unroll
    for (int i = 0; i < 4; i++) {
        #pragma unroll
        for (int j = 0; j < 4; j++) {
            int row = brow + wm + i * 16 + grp;
            int col = bcol + wn + j * 8 + tig * 2;
            float* c0 = &C[(size_t)row * N + col];
            c0[0] = acc[i][j][0];
            c0[1] = acc[i][j][1];
            float* c1 = c0 + (size_t)8 * N;
            c1[0] = acc[i][j][2];
            c1[1] = acc[i][j][3];
        }
    }
}

// ---------------------------------------------------------------------------
// RMSNorm+RoPE for q,k (q pre-scaled by SCALE), v pass-through; writes bf16
// hi/lo split to g_h/g_l. One block per (token, head32).
// ---------------------------------------------------------------------------
__global__ __launch_bounds__(256) void split_kernel(
    const float* __restrict__ qkv, const float* __restrict__ cosb,
    const float* __restrict__ sinb, const float* __restrict__ qw,
    const float* __restrict__ kw, __nv_bfloat16* __restrict__ gh,
    __nv_bfloat16* __restrict__ gl)
{
    const int blk = blockIdx.x;
    const int h32 = blk & 31;
    const int bs  = blk >> 5;
    const int tid = threadIdx.x;

    const size_t base = (size_t)bs * F_ + h32 * HD_;
    float x = qkv[base + tid];
    float val;

    if (h32 < NH_ + NKV_) {
        float ss = x * x;
        #pragma unroll
        for (int m = 16; m; m >>= 1) ss += __shfl_xor_sync(~0u, ss, m);
        __shared__ float warpsum[8];
        __shared__ float xn_s[HD_];
        if ((tid & 31) == 0) warpsum[tid >> 5] = ss;
        __syncthreads();
        float tot = warpsum[0] + warpsum[1] + warpsum[2] + warpsum[3]
                  + warpsum[4] + warpsum[5] + warpsum[6] + warpsum[7];
        float inv = rsqrtf(tot * (1.0f / HD_) + EPS_);
        const float* w = (h32 < NH_) ? qw : kw;
        float xn = x * inv * (1.0f + w[tid]);
        xn_s[tid] = xn;
        __syncthreads();
        float rot = (tid < HD_ / 2) ? -xn_s[tid + HD_ / 2] : xn_s[tid - HD_ / 2];
        float c = cosb[(size_t)bs * HD_ + tid];
        float s = sinb[(size_t)bs * HD_ + tid];
        val = xn * c + rot * s;
        if (h32 < NH_) val *= SCALE_;
    } else {
        val = x;
    }

    __nv_bfloat16 hi = __float2bfloat16(val);
    gh[base + tid] = hi;
    gl[base + tid] = __float2bfloat16(val - __bfloat162float(hi));
}

// ---------------------------------------------------------------------------
// MMA flash attention (unchanged from R4)
// ---------------------------------------------------------------------------
#define QSTR 264
#define TK 32
#define FATTN_SMEM ((128 * QSTR * 2 + TK * QSTR * 4) * 2)

__global__ __launch_bounds__(256, 1) void fattn_kernel(
    const __nv_bfloat16* __restrict__ gh, const __nv_bfloat16* __restrict__ gl,
    float* __restrict__ aout)
{
    extern __shared__ __nv_bfloat16 sm[];
    __nv_bfloat16* QH = sm;
    __nv_bfloat16* QL = QH + 128 * QSTR;
    __nv_bfloat16* KH = QL + 128 * QSTR;
    __nv_bfloat16* KL = KH + TK * QSTR;
    __nv_bfloat16* VH = KL + TK * QSTR;
    __nv_bfloat16* VL = VH + TK * QSTR;

    const int tid = threadIdx.x;
    const int w = tid >> 5;
    const int l = tid & 31;

    const int qt = blockIdx.x & 15;
    const int h  = (blockIdx.x >> 4) & 15;
    const int b  = blockIdx.x >> 8;
    const int kvh = h >> 1;
    const int q0 = qt * 128;

    const size_t koff = (size_t)NH_ * HD_ + kvh * HD_;
    const size_t voff = (size_t)(NH_ + NKV_) * HD_ + kvh * HD_;

    for (int i = tid; i < 128 * 32; i += 256) {
        int r = i >> 5, c = i & 31;
        size_t src = ((size_t)(b * S_ + q0 + r)) * F_ + h * HD_ + c * 8;
        int dst = r * QSTR + c * 8;
        *(uint4*)(QH + dst) = *(const uint4*)(gh + src);
        *(uint4*)(QL + dst) = *(const uint4*)(gl + src);
    }

    float o[32][4];
    #pragma unroll
    for (int nt = 0; nt < 32; nt++)
        #pragma unroll
        for (int j = 0; j < 4; j++) o[nt][j] = 0.f;

    float m_lo = -1e30f, m_hi = -1e30f, l_lo = 0.f, l_hi = 0.f;

    const uint32_t qh_b = s2u(QH), ql_b = s2u(QL);
    const uint32_t kh_b = s2u(KH), kl_b = s2u(KL);
    const uint32_t vh_b = s2u(VH), vl_b = s2u(VL);

    const int qrow  = 16 * w + (l & 15);
    const int qcol8 = (l >> 4) << 3;
    const int krow  = (l & 7) + ((l >> 4) & 1) * 8;
    const int kcol8 = ((l >> 3) & 1) << 3;
    const int vrow  = l & 15;

    for (int kt = 0; kt < S_ / TK; kt++) {
        __syncthreads();
        for (int i = tid; i < TK * 32; i += 256) {
            int r = i >> 5, c = i & 31;
            size_t base = ((size_t)(b * S_ + kt * TK + r)) * F_;
            int dst = r * QSTR + c * 8;
            *(uint4*)(KH + dst) = *(const uint4*)(gh + base + koff + c * 8);
            *(uint4*)(KL + dst) = *(const uint4*)(gl + base + koff + c * 8);
            *(uint4*)(VH + dst) = *(const uint4*)(gh + base + voff + c * 8);
            *(uint4*)(VL + dst) = *(const uint4*)(gl + base + voff + c * 8);
        }
        __syncthreads();

        float sA[4][4];
        #pragma unroll
        for (int nt = 0; nt < 4; nt++)
            #pragma unroll
            for (int j = 0; j < 4; j++) sA[nt][j] = 0.f;

        #pragma unroll
        for (int ks = 0; ks < 16; ks++) {
            uint32_t ah[4], al[4];
            uint32_t qoff = (uint32_t)(qrow * QSTR + ks * 16 + qcol8) * 2;
            LDSM_X4(ah[0], ah[1], ah[2], ah[3], qh_b + qoff);
            LDSM_X4(al[0], al[1], al[2], al[3], ql_b + qoff);
            #pragma unroll
            for (int ntp = 0; ntp < 2; ntp++) {
                uint32_t bh[4], bl[4];
                uint32_t kofs = (uint32_t)((16 * ntp + krow) * QSTR + ks * 16 + kcol8) * 2;
                LDSM_X4(bh[0], bh[1], bh[2], bh[3], kh_b + kofs);
                LDSM_X4(bl[0], bl[1], bl[2], bl[3], kl_b + kofs);
                MMA_BF16(sA[2 * ntp],     ah, bh);
                MMA_BF16(sA[2 * ntp],     ah, bl);
                MMA_BF16(sA[2 * ntp],     al, bh);
                MMA_BF16(sA[2 * ntp + 1], ah, bh + 2);
                MMA_BF16(sA[2 * ntp + 1], ah, bl + 2);
                MMA_BF16(sA[2 * ntp + 1], al, bh + 2);
            }
        }

        float tmax_lo = sA[0][0], tmax_hi = sA[0][2];
        #pragma unroll
        for (int nt = 0; nt < 4; nt++) {
            tmax_lo = fmaxf(tmax_lo, fmaxf(sA[nt][0], sA[nt][1]));
            tmax_hi = fmaxf(tmax_hi, fmaxf(sA[nt][2], sA[nt][3]));
        }
        tmax_lo = fmaxf(tmax_lo, __shfl_xor_sync(~0u, tmax_lo, 1));
        tmax_lo = fmaxf(tmax_lo, __shfl_xor_sync(~0u, tmax_lo, 2));
        tmax_hi = fmaxf(tmax_hi, __shfl_xor_sync(~0u, tmax_hi, 1));
        tmax_hi = fmaxf(tmax_hi, __shfl_xor_sync(~0u, tmax_hi, 2));

        float mn_lo = fmaxf(m_lo, tmax_lo);
        float mn_hi = fmaxf(m_hi, tmax_hi);
        float sc_lo = ex2f((m_lo - mn_lo) * LOG2E_);
        float sc_hi = ex2f((m_hi - mn_hi) * LOG2E_);
        m_lo = mn_lo; m_hi = mn_hi;

        float rs_lo = 0.f, rs_hi = 0.f;
        #pragma unroll
        for (int nt = 0; nt < 4; nt++) {
            sA[nt][0] = ex2f((sA[nt][0] - m_lo) * LOG2E_);
            sA[nt][1] = ex2f((sA[nt][1] - m_lo) * LOG2E_);
            sA[nt][2] = ex2f((sA[nt][2] - m_hi) * LOG2E_);
            sA[nt][3] = ex2f((sA[nt][3] - m_hi) * LOG2E_);
            rs_lo += sA[nt][0] + sA[nt][1];
            rs_hi += sA[nt][2] + sA[nt][3];
        }
        rs_lo += __shfl_xor_sync(~0u, rs_lo, 1);
        rs_lo += __shfl_xor_sync(~0u, rs_lo, 2);
        rs_hi += __shfl_xor_sync(~0u, rs_hi, 1);
        rs_hi += __shfl_xor_sync(~0u, rs_hi, 2);
        l_lo = l_lo * sc_lo + rs_lo;
        l_hi = l_hi * sc_hi + rs_hi;

        #pragma unroll
        for (int nt = 0; nt < 32; nt++) {
            o[nt][0] *= sc_lo; o[nt][1] *= sc_lo;
            o[nt][2] *= sc_hi; o[nt][3] *= sc_hi;
        }

        uint32_t aPh[2][4], aPl[2][4];
        #pragma unroll
        for (int ksp = 0; ksp < 2; ksp++) {
            #pragma unroll
            for (int q = 0; q < 4; q++) {
                int nt = 2 * ksp + (q >> 1);
                int j0 = (q & 1) * 2;
                float p0 = sA[nt][j0], p1 = sA[nt][j0 + 1];
                float h0 = bf_round(p0), h1 = bf_round(p1);
                aPh[ksp][q] = pack_bf16(h0, h1);
                aPl[ksp][q] = pack_bf16(p0 - h0, p1 - h1);
            }
        }

        #pragma unroll
        for (int ksp = 0; ksp < 2; ksp++) {
            #pragma unroll
            for (int nt = 0; nt < 32; nt++) {
                uint32_t vofs = (uint32_t)((16 * ksp + vrow) * QSTR + nt * 8) * 2;
                uint32_t bv[2], bw[2];
                LDSM_X2T(bv[0], bv[1], vh_b + vofs);
                LDSM_X2T(bw[0], bw[1], vl_b + vofs);
                MMA_BF16(o[nt], aPh[ksp], bv);
                MMA_BF16(o[nt], aPh[ksp], bw);
                MMA_BF16(o[nt], aPl[ksp], bv);
            }
        }
    }

    float inv_lo = 1.0f / l_lo;
    float inv_hi = 1.0f / l_hi;
    const int row_lo = q0 + 16 * w + (l >> 2);
    const int col0 = h * HD_ + 2 * (l & 3);
    #pragma unroll
    for (int nt = 0; nt < 32; nt++) {
        float2 vlo = make_float2(o[nt][0] * inv_lo, o[nt][1] * inv_lo);
        float2 vhi = make_float2(o[nt][2] * inv_hi, o[nt][3] * inv_hi);
        *(float2*)(aout + (size_t)(b * S_ + row_lo)     * (NH_ * HD_) + col0 + nt * 8) = vlo;
        *(float2*)(aout + (size_t)(b * S_ + row_lo + 8) * (NH_ * HD_) + col0 + nt * 8) = vhi;
    }
}

// ---------------------------------------------------------------------------
// Launch
// ---------------------------------------------------------------------------
extern "C" void kernel_launch(void* const* d_in, const int* in_sizes, int n_in,
                              void* d_out, int out_size)
{
    const float* hidden = (const float*)d_in[0];
    const float* cosb   = (const float*)d_in[1];
    const float* sinb   = (const float*)d_in[2];
    const float* w_qkv  = (const float*)d_in[3];
    const float* w_o    = (const float*)d_in[4];
    const float* q_w    = (const float*)d_in[5];
    const float* k_w    = (const float*)d_in[6];
    float* out = (float*)d_out;

    float* qkv; cudaGetSymbolAddress((void**)&qkv, g_qkv);
    float* ao;  cudaGetSymbolAddress((void**)&ao,  g_ao);
    __nv_bfloat16 *gh, *gl, *hidh, *hidl, *wqh, *wql, *woh, *wol, *aoh, *aol;
    cudaGetSymbolAddress((void**)&gh,   g_h);
    cudaGetSymbolAddress((void**)&gl,   g_l);
    cudaGetSymbolAddress((void**)&hidh, g_hidh);
    cudaGetSymbolAddress((void**)&hidl, g_hidl);
    cudaGetSymbolAddress((void**)&wqh,  g_wqh);
    cudaGetSymbolAddress((void**)&wql,  g_wql);
    cudaGetSymbolAddress((void**)&woh,  g_woh);
    cudaGetSymbolAddress((void**)&wol,  g_wol);
    cudaGetSymbolAddress((void**)&aoh,  g_aoh);
    cudaGetSymbolAddress((void**)&aol,  g_aol);

    cudaFuncSetAttribute(fattn_kernel, cudaFuncAttributeMaxDynamicSharedMemorySize,
                         FATTN_SMEM);
    cudaFuncSetAttribute(gemm_bf16x3_kernel, cudaFuncAttributeMaxDynamicSharedMemorySize,
                         GEMM_SMEM);

    // 0) Split GEMM inputs to bf16 hi/lo
    {
        int n4;
        n4 = M1_ * HID_ / 4;
        split_f32_kernel<<<(n4 + 255) / 256, 256>>>(hidden, hidh, hidl, n4);
        n4 = HID_ * F_ / 4;
        split_f32_kernel<<<(n4 + 255) / 256, 256>>>(w_qkv, wqh, wql, n4);
        n4 = (NH_ * HD_) * HID_ / 4;
        split_f32_kernel<<<(n4 + 255) / 256, 256>>>(w_o, woh, wol, n4);
    }

    // 1) QKV projection: [4096,2048] @ [2048,8192]
    {
        dim3 grid(F_ / 128, M1_ / 128);
        gemm_bf16x3_kernel<<<grid, 256, GEMM_SMEM>>>(hidh, hidl, wqh, wql,
                                                     qkv, M1_, F_, HID_);
    }

    // 2) RMSNorm + RoPE + bf16 hi/lo split for attention
    split_kernel<<<M1_ * 32, 256>>>(qkv, cosb, sinb, q_w, k_w, gh, gl);

    // 3) Flash attention (tensor cores)
    fattn_kernel<<<B_ * NH_ * (S_ / 128), 256, FATTN_SMEM>>>(gh, gl, ao);

    // 4) Split attention output, then O projection: [4096,4096] @ [4096,2048]
    {
        int n4 = M1_ * (NH_ * HD_) / 4;
        split_f32_kernel<<<(n4 + 255) / 256, 256>>>(ao, aoh, aol, n4);
        dim3 grid(HID_ / 128, M1_ / 128);
        gemm_bf16x3_kernel<<<grid, 256, GEMM_SMEM>>>(aoh, aol, woh, wol,
                                                     out, M1_, HID_, NH_ * HD_);
    }
}